// round 2
// baseline (speedup 1.0000x reference)
#include <cuda_runtime.h>
#include <math.h>

#define NB 8
#define NT 2048
#define NE 64
#define NH 8
#define NDK 8
#define NFF 256
#define NROWS (NB*NT)

typedef unsigned long long u64;

__device__ __forceinline__ u64 pk2(float x, float y){ u64 r; asm("mov.b64 %0,{%1,%2};":"=l"(r):"f"(x),"f"(y)); return r; }
__device__ __forceinline__ void upk2(float&x,float&y,u64 v){ asm("mov.b64 {%0,%1},%2;":"=f"(x),"=f"(y):"l"(v)); }
__device__ __forceinline__ u64 ffma2(u64 a,u64 b,u64 c){ u64 r; asm("fma.rn.f32x2 %0,%1,%2,%3;":"=l"(r):"l"(a),"l"(b),"l"(c)); return r; }
__device__ __forceinline__ u64 fadd2(u64 a,u64 b){ u64 r; asm("add.rn.f32x2 %0,%1,%2;":"=l"(r):"l"(a),"l"(b)); return r; }

// ---- scratch ----
__device__ float g_q[NB*NH*NT*NDK];     // [bh][t][d], pre-scaled 1/sqrt(DK)
__device__ float g_k[NB*NH*NDK*NT];     // [bh][d][t]
__device__ float g_v[NB*NH*NDK*NT];     // [bh][d][t]
__device__ float g_attn[NROWS*NE];
__device__ float g_x1[NROWS*NE];
__device__ float g_qout[NROWS*NE];
__device__ float g_hid[NROWS*NFF];
__device__ float g_W1t[NE*NFF];         // [e][f]
__device__ float g_W2t[NFF*NE];         // [f][j]

__global__ void k_transpose(const float* __restrict__ W1, const float* __restrict__ W2){
    int i = blockIdx.x*256 + threadIdx.x;
    if (i < NE*NFF){
        int e = i / NFF, f = i % NFF;
        g_W1t[i] = W1[f*NE + e];
        int f2 = i / NE, j = i % NE;
        g_W2t[i] = W2[j*NFF + f2];
    }
}

// ---- K1: QKV projection + cos(. + theta) ----
// 64 rows/block, 256 threads, thread = 4 rows x 4 cols (16 FMA : 5 LDS)
#define QKV_SMEM ((64*68 + 64*68 + 64*69 + 3*64)*4)
__global__ __launch_bounds__(256) void k_qkv(
    const float* __restrict__ x,
    const float* __restrict__ Wq, const float* __restrict__ bq,
    const float* __restrict__ Wk, const float* __restrict__ bk,
    const float* __restrict__ Wv, const float* __restrict__ bv,
    const float* __restrict__ th)
{
    extern __shared__ float sm[];
    float* xs = sm;             // [64][68]
    float* Wt = sm + 64*68;     // [64][68]  (w4 loads, float4-aligned pitch)
    float* st = Wt + 64*68;     // [64][69]  staging (pitch 69 -> <=2-way on write)
    float* bs = st + 64*69;     // [3][64]
    int tid = threadIdx.x;
    int row0 = blockIdx.x*64;
    int b = row0 >> 11, t0 = row0 & (NT-1);

    for (int i = tid; i < 64*16; i += 256){
        int r = i >> 4, c = i & 15;
        *(float4*)(xs + r*68 + c*4) = *(const float4*)(x + (row0 + r)*NE + c*4);
    }
    if (tid < 64){ bs[tid] = bq[tid]; bs[64 + tid] = bk[tid]; bs[128 + tid] = bv[tid]; }
    const float theta = *th;
    int cx = tid & 15, ry = tid >> 4;
    const float* Ws[3] = {Wq, Wk, Wv};

    for (int p = 0; p < 3; ++p){
        __syncthreads();
        for (int i = tid; i < 4096; i += 256){
            int j = i >> 6, e = i & 63;
            Wt[e*68 + j] = Ws[p][i];
        }
        __syncthreads();
        float acc[4][4];
        #pragma unroll
        for (int r = 0; r < 4; ++r){ acc[r][0]=0.f; acc[r][1]=0.f; acc[r][2]=0.f; acc[r][3]=0.f; }
        #pragma unroll 8
        for (int e = 0; e < 64; ++e){
            float4 w = *(float4*)(Wt + e*68 + cx*4);
            #pragma unroll
            for (int r = 0; r < 4; ++r){
                float xv = xs[(ry*4 + r)*68 + e];
                acc[r][0] = fmaf(xv, w.x, acc[r][0]);
                acc[r][1] = fmaf(xv, w.y, acc[r][1]);
                acc[r][2] = fmaf(xv, w.z, acc[r][2]);
                acc[r][3] = fmaf(xv, w.w, acc[r][3]);
            }
        }
        int j0 = cx*4;
        float4 b4 = *(float4*)(bs + p*64 + j0);
        if (p == 0){
            int h = j0 >> 3, d0 = j0 & 7;
            #pragma unroll
            for (int r = 0; r < 4; ++r){
                int t = t0 + ry*4 + r;
                float4 o;
                o.x = cosf(acc[r][0] + b4.x + theta) * 0.35355339059327373f;
                o.y = cosf(acc[r][1] + b4.y + theta) * 0.35355339059327373f;
                o.z = cosf(acc[r][2] + b4.z + theta) * 0.35355339059327373f;
                o.w = cosf(acc[r][3] + b4.w + theta) * 0.35355339059327373f;
                *(float4*)(g_q + ((u64)(b*NH + h)*NT + t)*NDK + d0) = o;
            }
        } else {
            __syncthreads();
            float bb[4] = {b4.x, b4.y, b4.z, b4.w};
            #pragma unroll
            for (int c = 0; c < 4; ++c)
                #pragma unroll
                for (int r = 0; r < 4; ++r)
                    st[(j0 + c)*69 + ry*4 + r] = cosf(acc[r][c] + bb[c] + theta);
            __syncthreads();
            float* dst = (p == 1) ? g_k : g_v;
            for (int i = tid; i < 64*16; i += 256){
                int j = i >> 4, part = i & 15;
                int h = j >> 3, d = j & 7;
                const float* sp = st + j*69 + part*4;
                float4 o; o.x = sp[0]; o.y = sp[1]; o.z = sp[2]; o.w = sp[3];
                *(float4*)(dst + ((b*NH + h)*NDK + d)*NT + t0 + part*4) = o;
            }
        }
    }
}

// ---- K2: attention, full K/V in smem, single-pass no-max softmax ----
__global__ void __launch_bounds__(512,1) k_attn()
{
    extern __shared__ float sm[];
    float* Ks = sm;                 // [8][2048]
    float* Vs = sm + NDK*NT;        // [8][2048]
    int bh  = blockIdx.y;
    int tid = threadIdx.x;
    const float* kg = g_k + bh*(NDK*NT);
    const float* vg = g_v + bh*(NDK*NT);
    for (int i = tid; i < NDK*NT/4; i += 512){
        ((float4*)Ks)[i] = ((const float4*)kg)[i];
        ((float4*)Vs)[i] = ((const float4*)vg)[i];
    }
    __syncthreads();

    int q0 = blockIdx.x*1024 + tid;       // queries q0 and q0+512
    u64 q2[2][8], o2[2][8], lsum[2];
    #pragma unroll
    for (int qq = 0; qq < 2; ++qq){
        const float* qp = g_q + ((u64)bh*NT + (q0 + qq*512))*NDK;
        float4 qa = *(const float4*)qp;
        float4 qb = *((const float4*)qp + 1);
        q2[qq][0] = pk2(qa.x, qa.x); q2[qq][1] = pk2(qa.y, qa.y);
        q2[qq][2] = pk2(qa.z, qa.z); q2[qq][3] = pk2(qa.w, qa.w);
        q2[qq][4] = pk2(qb.x, qb.x); q2[qq][5] = pk2(qb.y, qb.y);
        q2[qq][6] = pk2(qb.z, qb.z); q2[qq][7] = pk2(qb.w, qb.w);
        #pragma unroll
        for (int d = 0; d < 8; ++d) o2[qq][d] = 0ull;
        lsum[qq] = 0ull;
    }

    #pragma unroll 1
    for (int s = 0; s < NT; s += 4){
        u64 sA[2], sB[2];
        sA[0]=0ull; sA[1]=0ull; sB[0]=0ull; sB[1]=0ull;
        #pragma unroll
        for (int d = 0; d < 8; ++d){
            const u64* kp = (const u64*)(Ks + d*NT + s);
            u64 kab = kp[0], kcd = kp[1];
            #pragma unroll
            for (int qq = 0; qq < 2; ++qq){
                sA[qq] = ffma2(q2[qq][d], kab, sA[qq]);
                sB[qq] = ffma2(q2[qq][d], kcd, sB[qq]);
            }
        }
        u64 pA[2], pB[2];
        #pragma unroll
        for (int qq = 0; qq < 2; ++qq){
            float a,b,c,d2;
            upk2(a, b, sA[qq]); upk2(c, d2, sB[qq]);
            a = __expf(a); b = __expf(b); c = __expf(c); d2 = __expf(d2);
            pA[qq] = pk2(a, b); pB[qq] = pk2(c, d2);
            lsum[qq] = fadd2(lsum[qq], fadd2(pA[qq], pB[qq]));
        }
        #pragma unroll
        for (int d = 0; d < 8; ++d){
            const u64* vp = (const u64*)(Vs + d*NT + s);
            u64 vab = vp[0], vcd = vp[1];
            #pragma unroll
            for (int qq = 0; qq < 2; ++qq){
                o2[qq][d] = ffma2(pA[qq], vab, o2[qq][d]);
                o2[qq][d] = ffma2(pB[qq], vcd, o2[qq][d]);
            }
        }
    }

    int b = bh >> 3, h = bh & 7;
    #pragma unroll
    for (int qq = 0; qq < 2; ++qq){
        float lx, ly; upk2(lx, ly, lsum[qq]);
        float inv = 1.0f / (lx + ly);
        int t = q0 + qq*512;
        float* dst = g_attn + ((u64)b*NT + t)*NE + h*8;
        #pragma unroll
        for (int d = 0; d < 8; ++d){
            float ox, oy; upk2(ox, oy, o2[qq][d]);
            dst[d] = (ox + oy) * inv;
        }
    }
}

// ---- K3: Wo proj + residual + LN1 + qout ----
__global__ __launch_bounds__(256) void k_o_ln(
    const float* __restrict__ x, const float* __restrict__ Wo,
    const float* __restrict__ bo, const float* __restrict__ g1,
    const float* __restrict__ be1, const float* __restrict__ th)
{
    __shared__ float Wt[64*68];
    __shared__ float as[64*68];
    int tid = threadIdx.x;
    int row0 = blockIdx.x*64;
    for (int i = tid; i < 4096; i += 256){
        int j = i >> 6, e = i & 63;
        Wt[e*68 + j] = Wo[i];
    }
    for (int i = tid; i < 64*16; i += 256){
        int r = i >> 4, c = i & 15;
        *(float4*)(as + r*68 + c*4) = *(const float4*)(g_attn + (u64)(row0 + r)*NE + c*4);
    }
    __syncthreads();
    int cx = tid & 15, ry = tid >> 4;
    float acc[4][4];
    #pragma unroll
    for (int r = 0; r < 4; ++r){ acc[r][0]=0.f; acc[r][1]=0.f; acc[r][2]=0.f; acc[r][3]=0.f; }
    #pragma unroll 8
    for (int e = 0; e < 64; ++e){
        float4 w = *(float4*)(Wt + e*68 + cx*4);
        #pragma unroll
        for (int r = 0; r < 4; ++r){
            float av = as[(ry*4 + r)*68 + e];
            acc[r][0] = fmaf(av, w.x, acc[r][0]);
            acc[r][1] = fmaf(av, w.y, acc[r][1]);
            acc[r][2] = fmaf(av, w.z, acc[r][2]);
            acc[r][3] = fmaf(av, w.w, acc[r][3]);
        }
    }
    int j0 = cx*4;
    float4 bo4 = *(const float4*)(bo + j0);
    float4 g14 = *(const float4*)(g1 + j0);
    float4 be14 = *(const float4*)(be1 + j0);
    float ct = cosf(*th);
    #pragma unroll
    for (int r = 0; r < 4; ++r){
        int row = row0 + ry*4 + r;
        float4 xr = *(const float4*)(x + (u64)row*NE + j0);
        float a0 = acc[r][0] + bo4.x + xr.x;
        float a1 = acc[r][1] + bo4.y + xr.y;
        float a2 = acc[r][2] + bo4.z + xr.z;
        float a3 = acc[r][3] + bo4.w + xr.w;
        float s = a0 + a1 + a2 + a3;
        #pragma unroll
        for (int o = 8; o > 0; o >>= 1) s += __shfl_xor_sync(0xffffffffu, s, o);
        float mean = s * (1.0f/64.0f);
        float d0 = a0 - mean, d1 = a1 - mean, d2 = a2 - mean, d3 = a3 - mean;
        float vs = d0*d0 + d1*d1 + d2*d2 + d3*d3;
        #pragma unroll
        for (int o = 8; o > 0; o >>= 1) vs += __shfl_xor_sync(0xffffffffu, vs, o);
        float rstd = rsqrtf(vs * (1.0f/64.0f) + 1e-5f);
        float4 y;
        y.x = d0*rstd*g14.x + be14.x;
        y.y = d1*rstd*g14.y + be14.y;
        y.z = d2*rstd*g14.z + be14.z;
        y.w = d3*rstd*g14.w + be14.w;
        *(float4*)(g_x1 + (u64)row*NE + j0) = y;
        float4 qo;
        qo.x = cosf(y.x)*ct; qo.y = cosf(y.y)*ct;
        qo.z = cosf(y.z)*ct; qo.w = cosf(y.w)*ct;
        *(float4*)(g_qout + (u64)row*NE + j0) = qo;
    }
}

// ---- K4: FFN1: hid = relu(qout @ W1^T + b1), 64 rows/block ----
#define FFN1_SMEM ((64*260 + 64*68)*4)
__global__ __launch_bounds__(256,2) void k_ffn1(const float* __restrict__ b1)
{
    extern __shared__ float sm[];
    float* Ws = sm;              // [e][260]
    float* xs = sm + 64*260;     // [64][68]
    int tid = threadIdx.x;
    int row0 = blockIdx.x*64;
    for (int i = tid; i < 64*64; i += 256){
        int e = i >> 6, fq = i & 63;
        *(float4*)(Ws + e*260 + fq*4) = *(const float4*)(g_W1t + e*NFF + fq*4);
    }
    for (int i = tid; i < 64*16; i += 256){
        int r = i >> 4, c = i & 15;
        *(float4*)(xs + r*68 + c*4) = *(const float4*)(g_qout + (u64)(row0 + r)*NE + c*4);
    }
    __syncthreads();
    int cx = tid & 63, rg = tid >> 6;   // rows rg*16..+15, cols cx*4..+3
    float acc[16][4];
    #pragma unroll
    for (int i = 0; i < 16; ++i){ acc[i][0]=0.f; acc[i][1]=0.f; acc[i][2]=0.f; acc[i][3]=0.f; }
    #pragma unroll 4
    for (int e = 0; e < 64; ++e){
        float4 w = *(float4*)(Ws + e*260 + cx*4);
        #pragma unroll
        for (int i = 0; i < 16; ++i){
            float xv = xs[(rg*16 + i)*68 + e];
            acc[i][0] = fmaf(xv, w.x, acc[i][0]);
            acc[i][1] = fmaf(xv, w.y, acc[i][1]);
            acc[i][2] = fmaf(xv, w.z, acc[i][2]);
            acc[i][3] = fmaf(xv, w.w, acc[i][3]);
        }
    }
    float4 b4 = *(const float4*)(b1 + cx*4);
    #pragma unroll
    for (int i = 0; i < 16; ++i){
        int row = row0 + rg*16 + i;
        float4 o;
        o.x = fmaxf(acc[i][0] + b4.x, 0.f);
        o.y = fmaxf(acc[i][1] + b4.y, 0.f);
        o.z = fmaxf(acc[i][2] + b4.z, 0.f);
        o.w = fmaxf(acc[i][3] + b4.w, 0.f);
        *(float4*)(g_hid + (u64)row*NFF + cx*4) = o;
    }
}

// ---- K5: FFN2 + residual + LN2 -> out, 32 rows/block ----
#define FFN2_SMEM ((256*68 + 32*260)*4)
__global__ __launch_bounds__(256,2) void k_ffn2(
    const float* __restrict__ b2, const float* __restrict__ g2,
    const float* __restrict__ be2, float* __restrict__ out)
{
    extern __shared__ float sm[];
    float* Ws = sm;              // [f][68]
    float* hs = sm + 256*68;     // [32][260]
    int tid = threadIdx.x;
    int row0 = blockIdx.x*32;
    for (int i = tid; i < 256*16; i += 256){
        int f = i >> 4, jq = i & 15;
        *(float4*)(Ws + f*68 + jq*4) = *(const float4*)(g_W2t + f*NE + jq*4);
    }
    for (int i = tid; i < 32*64; i += 256){
        int r = i >> 6, c = i & 63;
        *(float4*)(hs + r*260 + c*4) = *(const float4*)(g_hid + (u64)(row0 + r)*NFF + c*4);
    }
    __syncthreads();
    int cx = tid & 15, ry = tid >> 4;   // rows ry*2, ry*2+1; cols cx*4..+3
    float acc[2][4];
    acc[0][0]=0.f;acc[0][1]=0.f;acc[0][2]=0.f;acc[0][3]=0.f;
    acc[1][0]=0.f;acc[1][1]=0.f;acc[1][2]=0.f;acc[1][3]=0.f;
    const float* h0p = hs + (ry*2)*260;
    const float* h1p = hs + (ry*2 + 1)*260;
    #pragma unroll 8
    for (int f = 0; f < 256; ++f){
        float4 w = *(float4*)(Ws + f*68 + cx*4);
        float h0 = h0p[f], h1 = h1p[f];
        acc[0][0] = fmaf(h0, w.x, acc[0][0]);
        acc[0][1] = fmaf(h0, w.y, acc[0][1]);
        acc[0][2] = fmaf(h0, w.z, acc[0][2]);
        acc[0][3] = fmaf(h0, w.w, acc[0][3]);
        acc[1][0] = fmaf(h1, w.x, acc[1][0]);
        acc[1][1] = fmaf(h1, w.y, acc[1][1]);
        acc[1][2] = fmaf(h1, w.z, acc[1][2]);
        acc[1][3] = fmaf(h1, w.w, acc[1][3]);
    }
    int j0 = cx*4;
    float4 b4 = *(const float4*)(b2 + j0);
    float4 g24 = *(const float4*)(g2 + j0);
    float4 be24 = *(const float4*)(be2 + j0);
    #pragma unroll
    for (int r = 0; r < 2; ++r){
        int row = row0 + ry*2 + r;
        float4 xr = *(const float4*)(g_x1 + (u64)row*NE + j0);
        float a0 = acc[r][0] + b4.x + xr.x;
        float a1 = acc[r][1] + b4.y + xr.y;
        float a2 = acc[r][2] + b4.z + xr.z;
        float a3 = acc[r][3] + b4.w + xr.w;
        float s = a0 + a1 + a2 + a3;
        #pragma unroll
        for (int o = 8; o > 0; o >>= 1) s += __shfl_xor_sync(0xffffffffu, s, o);
        float mean = s * (1.0f/64.0f);
        float d0 = a0 - mean, d1 = a1 - mean, d2 = a2 - mean, d3 = a3 - mean;
        float vs = d0*d0 + d1*d1 + d2*d2 + d3*d3;
        #pragma unroll
        for (int o = 8; o > 0; o >>= 1) vs += __shfl_xor_sync(0xffffffffu, vs, o);
        float rstd = rsqrtf(vs * (1.0f/64.0f) + 1e-5f);
        float4 y;
        y.x = d0*rstd*g24.x + be24.x;
        y.y = d1*rstd*g24.y + be24.y;
        y.z = d2*rstd*g24.z + be24.z;
        y.w = d3*rstd*g24.w + be24.w;
        *(float4*)(out + (u64)row*NE + j0) = y;
    }
}

extern "C" void kernel_launch(void* const* d_in, const int* in_sizes, int n_in,
                              void* d_out, int out_size)
{
    const float* x   = (const float*)d_in[0];
    const float* Wq  = (const float*)d_in[1];
    const float* bq  = (const float*)d_in[2];
    const float* Wk  = (const float*)d_in[3];
    const float* bk  = (const float*)d_in[4];
    const float* Wv  = (const float*)d_in[5];
    const float* bv  = (const float*)d_in[6];
    const float* Wo  = (const float*)d_in[7];
    const float* bo  = (const float*)d_in[8];
    const float* tha = (const float*)d_in[9];
    const float* thf = (const float*)d_in[10];
    const float* W1  = (const float*)d_in[11];
    const float* b1  = (const float*)d_in[12];
    const float* W2  = (const float*)d_in[13];
    const float* b2  = (const float*)d_in[14];
    const float* g1  = (const float*)d_in[15];
    const float* be1 = (const float*)d_in[16];
    const float* g2  = (const float*)d_in[17];
    const float* be2 = (const float*)d_in[18];
    float* out = (float*)d_out;

    cudaFuncSetAttribute(k_qkv,  cudaFuncAttributeMaxDynamicSharedMemorySize, QKV_SMEM);
    cudaFuncSetAttribute(k_attn, cudaFuncAttributeMaxDynamicSharedMemorySize, 131072);
    cudaFuncSetAttribute(k_ffn1, cudaFuncAttributeMaxDynamicSharedMemorySize, FFN1_SMEM);
    cudaFuncSetAttribute(k_ffn2, cudaFuncAttributeMaxDynamicSharedMemorySize, FFN2_SMEM);

    k_transpose<<<64, 256>>>(W1, W2);
    k_qkv<<<NROWS/64, 256, QKV_SMEM>>>(x, Wq, bq, Wk, bk, Wv, bv, tha);
    k_attn<<<dim3(2, 64), 512, 131072>>>();
    k_o_ln<<<NROWS/64, 256>>>(x, Wo, bo, g1, be1, thf);
    k_ffn1<<<NROWS/64, 256, FFN1_SMEM>>>(b1);
    k_ffn2<<<NROWS/32, 256, FFN2_SMEM>>>(b2, g2, be2, out);
}

// round 3
// speedup vs baseline: 1.4609x; 1.4609x over previous
#include <cuda_runtime.h>
#include <math.h>

#define NB 8
#define NT 2048
#define NE 64
#define NH 8
#define NDK 8
#define NFF 256
#define NROWS (NB*NT)

typedef unsigned long long u64;

__device__ __forceinline__ u64 pk2(float x, float y){ u64 r; asm("mov.b64 %0,{%1,%2};":"=l"(r):"f"(x),"f"(y)); return r; }
__device__ __forceinline__ void upk2(float&x,float&y,u64 v){ asm("mov.b64 {%0,%1},%2;":"=f"(x),"=f"(y):"l"(v)); }
__device__ __forceinline__ u64 ffma2(u64 a,u64 b,u64 c){ u64 r; asm("fma.rn.f32x2 %0,%1,%2,%3;":"=l"(r):"l"(a),"l"(b),"l"(c)); return r; }
__device__ __forceinline__ u64 fadd2(u64 a,u64 b){ u64 r; asm("add.rn.f32x2 %0,%1,%2;":"=l"(r):"l"(a),"l"(b)); return r; }

// ---- scratch: ALL activations in row-major [row][64] (fully coalesced) ----
__device__ float g_q[NROWS*NE];     // cos(xWq+b+th)/sqrt(8), col = h*8+d
__device__ float g_k[NROWS*NE];
__device__ float g_v[NROWS*NE];
__device__ float g_attn[NROWS*NE];
__device__ float g_x1[NROWS*NE];
__device__ float g_qout[NROWS*NE];
__device__ float g_hid[NROWS*NFF];
__device__ float g_W1t[NE*NFF];     // [e][f]
__device__ float g_W2t[NFF*NE];     // [f][j]

__global__ void k_transpose(const float* __restrict__ W1, const float* __restrict__ W2){
    int i = blockIdx.x*256 + threadIdx.x;
    if (i < NE*NFF){
        int e = i / NFF, f = i % NFF;
        g_W1t[i] = W1[f*NE + e];
        int f2 = i / NE, j = i % NE;
        g_W2t[i] = W2[j*NFF + f2];
    }
}

// ---- K1: QKV projection + cos(.+theta). 32 rows/block, 512 blocks.
// thread = 4 rows x 1 col-pair; f32x2 FMA; x pre-duplicated in smem.
#define QKV_SMEM ((32*130 + 64*66)*4)
__global__ __launch_bounds__(256) void k_qkv(
    const float* __restrict__ x,
    const float* __restrict__ Wq, const float* __restrict__ bq,
    const float* __restrict__ Wk, const float* __restrict__ bk,
    const float* __restrict__ Wv, const float* __restrict__ bv,
    const float* __restrict__ th)
{
    extern __shared__ float sm[];
    float* xs2 = sm;            // [32][130] duplicated pairs
    float* Wt  = sm + 32*130;   // [64][66]  Wt[e][j]
    int tid = threadIdx.x;
    int row0 = blockIdx.x*32;

    for (int i = tid; i < 32*64; i += 256){
        int r = i >> 6, c = i & 63;
        float v = x[(u64)(row0 + r)*NE + c];
        *(u64*)(xs2 + r*130 + c*2) = pk2(v, v);
    }
    const float theta = *th;
    int j2 = tid & 31, g = tid >> 5;
    int j0 = j2*2;
    const float* Ws[3]   = {Wq, Wk, Wv};
    const float* bias[3] = {bq, bk, bv};
    float* dsts[3] = {g_q, g_k, g_v};

    for (int p = 0; p < 3; ++p){
        __syncthreads();
        for (int i = tid; i < 4096; i += 256){
            int j = i >> 6, e = i & 63;
            Wt[e*66 + j] = Ws[p][j*64 + e];      // coalesced gmem, 2-way smem
        }
        __syncthreads();
        u64 acc[4] = {0ull,0ull,0ull,0ull};
        const float* xb = xs2 + (g*4)*130;
        #pragma unroll 8
        for (int e = 0; e < 64; ++e){
            u64 w = *(const u64*)(Wt + e*66 + j0);
            acc[0] = ffma2(*(const u64*)(xb +        e*2), w, acc[0]);
            acc[1] = ffma2(*(const u64*)(xb + 130  + e*2), w, acc[1]);
            acc[2] = ffma2(*(const u64*)(xb + 260  + e*2), w, acc[2]);
            acc[3] = ffma2(*(const u64*)(xb + 390  + e*2), w, acc[3]);
        }
        float2 bb = *(const float2*)(bias[p] + j0);
        float scale = (p == 0) ? 0.35355339059327373f : 1.0f;
        float* dst = dsts[p];
        #pragma unroll
        for (int r = 0; r < 4; ++r){
            float a0, a1; upk2(a0, a1, acc[r]);
            float2 o;
            o.x = cosf(a0 + bb.x + theta) * scale;
            o.y = cosf(a1 + bb.y + theta) * scale;
            *(float2*)(dst + (u64)(row0 + g*4 + r)*NE + j0) = o;
        }
    }
}

// ---- K2: attention. Full K/V in smem [d][t]; transpose during fill.
__global__ void __launch_bounds__(512,1) k_attn()
{
    extern __shared__ float sm[];
    float* Ks = sm;                 // [8][2048]
    float* Vs = sm + NDK*NT;
    int bh  = blockIdx.y;
    int b = bh >> 3, h = bh & 7;
    int tid = threadIdx.x;
    const float* kg = g_k + (u64)b*NT*NE + h*8;
    const float* vg = g_v + (u64)b*NT*NE + h*8;
    for (int i = tid; i < 2*NT; i += 512){
        int t = i & (NT-1), half = (i >> 11)*4;
        float4 kv = *(const float4*)(kg + (u64)t*NE + half);
        Ks[(half+0)*NT + t] = kv.x; Ks[(half+1)*NT + t] = kv.y;
        Ks[(half+2)*NT + t] = kv.z; Ks[(half+3)*NT + t] = kv.w;
        float4 vv = *(const float4*)(vg + (u64)t*NE + half);
        Vs[(half+0)*NT + t] = vv.x; Vs[(half+1)*NT + t] = vv.y;
        Vs[(half+2)*NT + t] = vv.z; Vs[(half+3)*NT + t] = vv.w;
    }
    __syncthreads();

    int q0 = blockIdx.x*1024 + tid;       // queries q0 and q0+512
    u64 q2[2][8], o2[2][8], lsum[2];
    #pragma unroll
    for (int qq = 0; qq < 2; ++qq){
        const float* qp = g_q + (u64)(b*NT + q0 + qq*512)*NE + h*8;
        float4 qa = *(const float4*)qp;
        float4 qb = *((const float4*)qp + 1);
        q2[qq][0] = pk2(qa.x, qa.x); q2[qq][1] = pk2(qa.y, qa.y);
        q2[qq][2] = pk2(qa.z, qa.z); q2[qq][3] = pk2(qa.w, qa.w);
        q2[qq][4] = pk2(qb.x, qb.x); q2[qq][5] = pk2(qb.y, qb.y);
        q2[qq][6] = pk2(qb.z, qb.z); q2[qq][7] = pk2(qb.w, qb.w);
        #pragma unroll
        for (int d = 0; d < 8; ++d) o2[qq][d] = 0ull;
        lsum[qq] = 0ull;
    }

    #pragma unroll 1
    for (int s = 0; s < NT; s += 4){
        u64 sA[2], sB[2];
        sA[0]=0ull; sA[1]=0ull; sB[0]=0ull; sB[1]=0ull;
        #pragma unroll
        for (int d = 0; d < 8; ++d){
            const u64* kp = (const u64*)(Ks + d*NT + s);
            u64 kab = kp[0], kcd = kp[1];
            #pragma unroll
            for (int qq = 0; qq < 2; ++qq){
                sA[qq] = ffma2(q2[qq][d], kab, sA[qq]);
                sB[qq] = ffma2(q2[qq][d], kcd, sB[qq]);
            }
        }
        u64 pA[2], pB[2];
        #pragma unroll
        for (int qq = 0; qq < 2; ++qq){
            float a,bv_,c,d2;
            upk2(a, bv_, sA[qq]); upk2(c, d2, sB[qq]);
            a = __expf(a); bv_ = __expf(bv_); c = __expf(c); d2 = __expf(d2);
            pA[qq] = pk2(a, bv_); pB[qq] = pk2(c, d2);
            lsum[qq] = fadd2(lsum[qq], fadd2(pA[qq], pB[qq]));
        }
        #pragma unroll
        for (int d = 0; d < 8; ++d){
            const u64* vp = (const u64*)(Vs + d*NT + s);
            u64 vab = vp[0], vcd = vp[1];
            #pragma unroll
            for (int qq = 0; qq < 2; ++qq){
                o2[qq][d] = ffma2(pA[qq], vab, o2[qq][d]);
                o2[qq][d] = ffma2(pB[qq], vcd, o2[qq][d]);
            }
        }
    }

    #pragma unroll
    for (int qq = 0; qq < 2; ++qq){
        float lx, ly; upk2(lx, ly, lsum[qq]);
        float inv = 1.0f / (lx + ly);
        int t = q0 + qq*512;
        float* dst = g_attn + (u64)(b*NT + t)*NE + h*8;
        float o[8];
        #pragma unroll
        for (int d = 0; d < 8; ++d){
            float ox, oy; upk2(ox, oy, o2[qq][d]);
            o[d] = (ox + oy) * inv;
        }
        *(float4*)dst       = make_float4(o[0],o[1],o[2],o[3]);
        *((float4*)dst + 1) = make_float4(o[4],o[5],o[6],o[7]);
    }
}

// ---- K3: Wo proj + residual + LN1 + qout. 32 rows/block, 512 blocks. ----
#define OLN_SMEM ((32*130 + 64*66)*4)
__global__ __launch_bounds__(256) void k_o_ln(
    const float* __restrict__ x, const float* __restrict__ Wo,
    const float* __restrict__ bo, const float* __restrict__ g1,
    const float* __restrict__ be1, const float* __restrict__ th)
{
    extern __shared__ float sm[];
    float* as2 = sm;            // [32][130] dup
    float* Wt  = sm + 32*130;   // [64][66]
    int tid = threadIdx.x;
    int row0 = blockIdx.x*32;
    for (int i = tid; i < 32*64; i += 256){
        int r = i >> 6, c = i & 63;
        float v = g_attn[(u64)(row0 + r)*NE + c];
        *(u64*)(as2 + r*130 + c*2) = pk2(v, v);
    }
    for (int i = tid; i < 4096; i += 256){
        int j = i >> 6, e = i & 63;
        Wt[e*66 + j] = Wo[j*64 + e];
    }
    __syncthreads();
    int j2 = tid & 31, g = tid >> 5;
    int j0 = j2*2;
    u64 acc[4] = {0ull,0ull,0ull,0ull};
    const float* ab = as2 + (g*4)*130;
    #pragma unroll 8
    for (int e = 0; e < 64; ++e){
        u64 w = *(const u64*)(Wt + e*66 + j0);
        acc[0] = ffma2(*(const u64*)(ab +       e*2), w, acc[0]);
        acc[1] = ffma2(*(const u64*)(ab + 130 + e*2), w, acc[1]);
        acc[2] = ffma2(*(const u64*)(ab + 260 + e*2), w, acc[2]);
        acc[3] = ffma2(*(const u64*)(ab + 390 + e*2), w, acc[3]);
    }
    float2 bo2  = *(const float2*)(bo + j0);
    float2 g12  = *(const float2*)(g1 + j0);
    float2 be12 = *(const float2*)(be1 + j0);
    float ct = cosf(*th);
    #pragma unroll
    for (int r = 0; r < 4; ++r){
        int row = row0 + g*4 + r;
        float2 xr = *(const float2*)(x + (u64)row*NE + j0);
        float a0, a1; upk2(a0, a1, acc[r]);
        a0 += bo2.x + xr.x;
        a1 += bo2.y + xr.y;
        float s = a0 + a1;
        #pragma unroll
        for (int o = 16; o > 0; o >>= 1) s += __shfl_xor_sync(0xffffffffu, s, o);
        float mean = s * (1.0f/64.0f);
        float d0 = a0 - mean, d1 = a1 - mean;
        float vs = d0*d0 + d1*d1;
        #pragma unroll
        for (int o = 16; o > 0; o >>= 1) vs += __shfl_xor_sync(0xffffffffu, vs, o);
        float rstd = rsqrtf(vs * (1.0f/64.0f) + 1e-5f);
        float2 y;
        y.x = d0*rstd*g12.x + be12.x;
        y.y = d1*rstd*g12.y + be12.y;
        *(float2*)(g_x1 + (u64)row*NE + j0) = y;
        float2 qo; qo.x = cosf(y.x)*ct; qo.y = cosf(y.y)*ct;
        *(float2*)(g_qout + (u64)row*NE + j0) = qo;
    }
}

// ---- K4: FFN1 relu(qout @ W1^T + b1). 32 rows/block, 512 blocks.
// thread = 8 rows x 2 col-pairs (pairs cq and cq+64, i.e. cols split by 128).
#define FFN1_SMEM ((64*260 + 32*130)*4)
__global__ __launch_bounds__(256,2) void k_ffn1(const float* __restrict__ b1)
{
    extern __shared__ float sm[];
    float* Ws  = sm;             // [e][260]
    float* xs2 = sm + 64*260;    // [32][130] dup
    int tid = threadIdx.x;
    int row0 = blockIdx.x*32;
    for (int i = tid; i < 64*64; i += 256){
        int e = i >> 6, q = i & 63;
        *(float4*)(Ws + e*260 + q*4) = *(const float4*)(g_W1t + e*NFF + q*4);
    }
    for (int i = tid; i < 32*64; i += 256){
        int r = i >> 6, c = i & 63;
        float v = g_qout[(u64)(row0 + r)*NE + c];
        *(u64*)(xs2 + r*130 + c*2) = pk2(v, v);
    }
    __syncthreads();
    int cq = tid & 63, rg = tid >> 6;   // rows rg*8..+7; col pairs cq, cq+64
    u64 acc[8][2];
    #pragma unroll
    for (int i = 0; i < 8; ++i){ acc[i][0] = 0ull; acc[i][1] = 0ull; }
    const float* xb = xs2 + (rg*8)*130;
    #pragma unroll 4
    for (int e = 0; e < 64; ++e){
        u64 w0 = *(const u64*)(Ws + e*260 + cq*2);
        u64 w1 = *(const u64*)(Ws + e*260 + cq*2 + 128);
        #pragma unroll
        for (int i = 0; i < 8; ++i){
            u64 xv = *(const u64*)(xb + i*130 + e*2);
            acc[i][0] = ffma2(xv, w0, acc[i][0]);
            acc[i][1] = ffma2(xv, w1, acc[i][1]);
        }
    }
    int c0 = cq*2;
    float2 ba = *(const float2*)(b1 + c0);
    float2 bb = *(const float2*)(b1 + c0 + 128);
    #pragma unroll
    for (int i = 0; i < 8; ++i){
        int row = row0 + rg*8 + i;
        float a0,a1,a2,a3;
        upk2(a0, a1, acc[i][0]);
        upk2(a2, a3, acc[i][1]);
        float2 o0; o0.x = fmaxf(a0 + ba.x, 0.f); o0.y = fmaxf(a1 + ba.y, 0.f);
        float2 o1; o1.x = fmaxf(a2 + bb.x, 0.f); o1.y = fmaxf(a3 + bb.y, 0.f);
        *(float2*)(g_hid + (u64)row*NFF + c0)       = o0;
        *(float2*)(g_hid + (u64)row*NFF + c0 + 128) = o1;
    }
}

// ---- K5: FFN2 + residual + LN2 -> out. 16 rows/block, 1024 blocks.
// thread = 2 rows x 1 col-pair.
#define FFN2_SMEM ((256*66 + 16*514)*4)
__global__ __launch_bounds__(256,2) void k_ffn2(
    const float* __restrict__ b2, const float* __restrict__ g2,
    const float* __restrict__ be2, float* __restrict__ out)
{
    extern __shared__ float sm[];
    float* Ws  = sm;             // [f][66]
    float* hs2 = sm + 256*66;    // [16][514] dup
    int tid = threadIdx.x;
    int row0 = blockIdx.x*16;
    for (int i = tid; i < 256*32; i += 256){
        int f = i >> 5, c2 = i & 31;
        *(float2*)(Ws + f*66 + c2*2) = *(const float2*)(g_W2t + f*NE + c2*2);
    }
    for (int i = tid; i < 16*256; i += 256){
        int r = i >> 8, c = i & 255;
        float v = g_hid[(u64)(row0 + r)*NFF + c];
        *(u64*)(hs2 + r*514 + c*2) = pk2(v, v);
    }
    __syncthreads();
    int cp = tid & 31, ry = tid >> 5;   // rows ry*2, ry*2+1; cols cp*2, cp*2+1
    int j0 = cp*2;
    u64 acc0 = 0ull, acc1 = 0ull;
    const float* h0p = hs2 + (ry*2)*514;
    const float* h1p = h0p + 514;
    #pragma unroll 8
    for (int f = 0; f < 256; ++f){
        u64 w = *(const u64*)(Ws + f*66 + j0);
        acc0 = ffma2(*(const u64*)(h0p + f*2), w, acc0);
        acc1 = ffma2(*(const u64*)(h1p + f*2), w, acc1);
    }
    float2 b4  = *(const float2*)(b2 + j0);
    float2 g24 = *(const float2*)(g2 + j0);
    float2 be24= *(const float2*)(be2 + j0);
    u64 accs[2] = {acc0, acc1};
    #pragma unroll
    for (int r = 0; r < 2; ++r){
        int row = row0 + ry*2 + r;
        float2 xr = *(const float2*)(g_x1 + (u64)row*NE + j0);
        float a0, a1; upk2(a0, a1, accs[r]);
        a0 += b4.x + xr.x;
        a1 += b4.y + xr.y;
        float s = a0 + a1;
        #pragma unroll
        for (int o = 16; o > 0; o >>= 1) s += __shfl_xor_sync(0xffffffffu, s, o);
        float mean = s * (1.0f/64.0f);
        float d0 = a0 - mean, d1 = a1 - mean;
        float vs = d0*d0 + d1*d1;
        #pragma unroll
        for (int o = 16; o > 0; o >>= 1) vs += __shfl_xor_sync(0xffffffffu, vs, o);
        float rstd = rsqrtf(vs * (1.0f/64.0f) + 1e-5f);
        float2 y;
        y.x = d0*rstd*g24.x + be24.x;
        y.y = d1*rstd*g24.y + be24.y;
        *(float2*)(out + (u64)row*NE + j0) = y;
    }
}

extern "C" void kernel_launch(void* const* d_in, const int* in_sizes, int n_in,
                              void* d_out, int out_size)
{
    const float* x   = (const float*)d_in[0];
    const float* Wq  = (const float*)d_in[1];
    const float* bq  = (const float*)d_in[2];
    const float* Wk  = (const float*)d_in[3];
    const float* bk  = (const float*)d_in[4];
    const float* Wv  = (const float*)d_in[5];
    const float* bv  = (const float*)d_in[6];
    const float* Wo  = (const float*)d_in[7];
    const float* bo  = (const float*)d_in[8];
    const float* tha = (const float*)d_in[9];
    const float* thf = (const float*)d_in[10];
    const float* W1  = (const float*)d_in[11];
    const float* b1  = (const float*)d_in[12];
    const float* W2  = (const float*)d_in[13];
    const float* b2  = (const float*)d_in[14];
    const float* g1  = (const float*)d_in[15];
    const float* be1 = (const float*)d_in[16];
    const float* g2  = (const float*)d_in[17];
    const float* be2 = (const float*)d_in[18];
    float* out = (float*)d_out;

    cudaFuncSetAttribute(k_qkv,  cudaFuncAttributeMaxDynamicSharedMemorySize, QKV_SMEM);
    cudaFuncSetAttribute(k_attn, cudaFuncAttributeMaxDynamicSharedMemorySize, 131072);
    cudaFuncSetAttribute(k_o_ln, cudaFuncAttributeMaxDynamicSharedMemorySize, OLN_SMEM);
    cudaFuncSetAttribute(k_ffn1, cudaFuncAttributeMaxDynamicSharedMemorySize, FFN1_SMEM);
    cudaFuncSetAttribute(k_ffn2, cudaFuncAttributeMaxDynamicSharedMemorySize, FFN2_SMEM);

    k_transpose<<<64, 256>>>(W1, W2);
    k_qkv<<<NROWS/32, 256, QKV_SMEM>>>(x, Wq, bq, Wk, bk, Wv, bv, tha);
    k_attn<<<dim3(2, 64), 512, 131072>>>();
    k_o_ln<<<NROWS/32, 256, OLN_SMEM>>>(x, Wo, bo, g1, be1, thf);
    k_ffn1<<<NROWS/32, 256, FFN1_SMEM>>>(b1);
    k_ffn2<<<NROWS/16, 256, FFN2_SMEM>>>(b2, g2, be2, out);
}